// round 2
// baseline (speedup 1.0000x reference)
#include <cuda_runtime.h>
#include <cuda_bf16.h>
#include <cstdint>

// ---------------- constants ----------------
#define B       256
#define T       32
#define XBC     1152        // 2*24*24
#define XT      (B*XBC)     // 294912 per step
#define C1      30
#define A1      400         // 20*20
#define L1SZ    (B*C1*A1)   // 3,072,000
#define P1      100         // 10*10
#define L3SZ    (B*C1*P1)   // 768,000
#define C2      100
#define A2      36          // 6*6
#define L2SZ    (B*C2*A2)   // 921,600
#define DW1CH   128         // 2 batches per chunk
#define DW2CH   64          // 4 batches per chunk

#define VTH1    15.0f
#define VTH2    10.0f
#define DEC     0.02f
#define ETA_P   0.004f
#define ETA_M   0.003f

// ---------------- persistent device state ----------------
__device__ float g_w1[1500];
__device__ float g_w2[75000];
__device__ float g_v1[L1SZ];
__device__ float g_v2[L2SZ];
__device__ float g_tp1[XT];
__device__ float g_to1[L1SZ];
__device__ float g_tp2[L3SZ];
__device__ float g_to2[L2SZ];
__device__ float g_z2[L1SZ];
__device__ float g_z3[L3SZ];
__device__ float g_z5[L2SZ];
__device__ float g_z6[B*C2];
__device__ float g_liv[B*10];
__device__ float g_lii[B*10];
__device__ float g_dw1p[DW1CH*1500];
__device__ float g_dw2p[DW2CH*75000];

// ---------------- init: zero state, copy weights ----------------
__global__ void k_init(const float* __restrict__ w1, const float* __restrict__ w2) {
    int i = blockIdx.x * blockDim.x + threadIdx.x;
    if (i < L1SZ) { g_v1[i] = 0.f; g_to1[i] = 0.f; }
    if (i < L2SZ) { g_v2[i] = 0.f; g_to2[i] = 0.f; }
    if (i < XT)   g_tp1[i] = 0.f;
    if (i < L3SZ) g_tp2[i] = 0.f;
    if (i < B*10) { g_liv[i] = 0.f; g_lii[i] = 0.f; }
    if (i < 1500)  g_w1[i] = w1[i];
    if (i < 75000) g_w2[i] = w2[i];
}

// ---------------- K1: conv1 + IAF + to1 trace; extra blocks do tp1 trace ----------------
__global__ void k1_conv1(const float* __restrict__ x, int t) {
    const float* xt = x + (size_t)t * XT;
    int tid = threadIdx.x;
    if (blockIdx.x >= B) {
        // tp1 trace blocks: 36 blocks * 8192 elems
        int base = (blockIdx.x - B) * 8192;
        #pragma unroll 4
        for (int r = 0; r < 32; r++) {
            int i = base + r * 256 + tid;
            float tt = g_tp1[i];
            g_tp1[i] = tt - DEC * tt + xt[i];
        }
        return;
    }
    int b = blockIdx.x;
    __shared__ float xs[XBC];
    __shared__ float w1T[50 * 32];   // transposed + padded to 32 oc
    for (int i = tid; i < XBC; i += 256) xs[i] = xt[b * XBC + i];
    for (int i = tid; i < 1600; i += 256) {
        int c = i >> 5, oc = i & 31;
        w1T[i] = (oc < 30) ? g_w1[oc * 50 + c] : 0.f;
    }
    __syncthreads();

    for (int p = tid; p < A1; p += 256) {
        int oh = p / 20, ow = p % 20;
        float patch[50];
        #pragma unroll
        for (int ic = 0; ic < 2; ic++)
            #pragma unroll
            for (int kh = 0; kh < 5; kh++)
                #pragma unroll
                for (int kw = 0; kw < 5; kw++)
                    patch[ic*25 + kh*5 + kw] = xs[ic*576 + (oh+kh)*24 + ow + kw];

        for (int g = 0; g < 8; g++) {
            float a0=0.f, a1=0.f, a2=0.f, a3=0.f;
            #pragma unroll
            for (int c = 0; c < 50; c++) {
                float4 w = *(const float4*)&w1T[c*32 + g*4];
                a0 = fmaf(patch[c], w.x, a0);
                a1 = fmaf(patch[c], w.y, a1);
                a2 = fmaf(patch[c], w.z, a2);
                a3 = fmaf(patch[c], w.w, a3);
            }
            float av[4] = {a0, a1, a2, a3};
            #pragma unroll
            for (int q = 0; q < 4; q++) {
                int oc = g*4 + q;
                if (oc < 30) {
                    int idx = b*12000 + oc*A1 + p;
                    float v = g_v1[idx] + av[q];
                    float z = (v > VTH1) ? 1.f : 0.f;
                    g_v1[idx] = v * (1.f - z);
                    g_z2[idx] = z;
                    float tt = g_to1[idx];
                    g_to1[idx] = tt - DEC * tt + z;
                }
            }
        }
    }
}

// ---------------- K2: maxpool 2x2 + tp2 trace ----------------
__global__ void k2_pool(void) {
    int e = blockIdx.x * 256 + threadIdx.x;   // < 768000
    int b = e / 3000, rem = e % 3000;
    int c = rem / 100, q = rem % 100;
    int oh = q / 10, ow = q % 10;
    int base = b*12000 + c*A1 + (oh*2)*20 + ow*2;
    float m = fmaxf(fmaxf(g_z2[base], g_z2[base+1]),
                    fmaxf(g_z2[base+20], g_z2[base+21]));
    g_z3[e] = m;
    float tt = g_tp2[e];
    g_tp2[e] = tt - DEC * tt + m;
}

// ---------------- K3: conv2 (x10) + IAF + to2 trace + z6 ----------------
// static smem: z3s(3000) + w2s(7500) = 42000 bytes, no attribute needed
__global__ void k3_conv2(void) {
    __shared__ float sm[10500];
    float* z3s = sm;          // 3000
    float* w2s = sm + 3000;   // 7500 (chunk of 3 ic), reused as staging later
    int b = blockIdx.x, tid = threadIdx.x;

    for (int i = tid; i < 3000; i += 128) z3s[i] = g_z3[b*3000 + i];

    float acc[36];
    #pragma unroll
    for (int p = 0; p < 36; p++) acc[p] = 0.f;

    for (int ic0 = 0; ic0 < 30; ic0 += 3) {
        __syncthreads();
        for (int i = tid; i < 7500; i += 128) {
            int oc = i / 75, cc = i % 75;
            w2s[i] = g_w2[oc*750 + ic0*25 + cc];
        }
        __syncthreads();
        if (tid < 100) {
            const float* wrow = &w2s[tid * 75];
            for (int cc = 0; cc < 75; cc++) {
                float w = wrow[cc];
                int ic = cc / 25;
                int r2 = cc - ic*25;
                int kh = r2 / 5, kw = r2 - kh*5;
                const float* zp = &z3s[(ic0 + ic)*100 + kh*10 + kw];
                #pragma unroll
                for (int p = 0; p < 36; p++)
                    acc[p] = fmaf(w, zp[(p/6)*10 + (p%6)], acc[p]);
            }
        }
    }
    __syncthreads();
    float* sacc = w2s;  // 3600 needed (fits in 7500)
    if (tid < 100) {
        #pragma unroll
        for (int p = 0; p < 36; p++) sacc[tid*36 + p] = acc[p];
    }
    __syncthreads();
    for (int i = tid; i < 3600; i += 128) {
        int idx = b*3600 + i;
        float v = g_v2[idx] + 10.0f * sacc[i];
        float z = (v > VTH2) ? 1.f : 0.f;
        g_v2[idx] = v * (1.f - z);
        g_z5[idx] = z;
        float tt = g_to2[idx];
        g_to2[idx] = tt - DEC * tt + z;
        sacc[i] = z;
    }
    __syncthreads();
    if (tid < 100) {
        float m = 0.f;
        #pragma unroll
        for (int p = 0; p < 36; p++) m = fmaxf(m, sacc[tid*36 + p]);
        g_z6[b*100 + tid] = m;
    }
}

// ---------------- K45: fused STDP weight-gradient partials (dw1 + dw2) ----------------
__global__ void k45_stdp(const float* __restrict__ x, int t) {
    __shared__ float smem[10304];
    int bi = blockIdx.x, tid = threadIdx.x;
    int wid = tid >> 5, ti = tid & 31;
    const float* xt = x + (size_t)t * XT;

    if (bi < DW1CH) {
        // ---- dw1: chunk of 2 batches, 10 warps = 10 j per jg, 3 jg groups ----
        float* pre1   = smem;          // 2*1152 interleaved (tp1, x)
        float* posts2 = smem + 2304;   // 2*4000 interleaved (z2, to1)
        int bch = bi;
        int i0 = ti;
        int ic_0 = i0 / 25, r_0 = i0 % 25;
        int ib0 = ic_0*576 + (r_0/5)*24 + (r_0%5);
        bool v1ok = (ti < 18);
        int i1 = ti + 32, ib1 = 0;
        if (v1ok) { int ic = i1/25, r = i1%25; ib1 = ic*576 + (r/5)*24 + (r%5); }

        for (int jg = 0; jg < 3; jg++) {
            int j = jg*10 + wid;
            float a0 = 0.f, a1 = 0.f;
            for (int bb = 0; bb < 2; bb++) {
                int b = bch*2 + bb;
                __syncthreads();
                for (int i2 = tid; i2 < XBC; i2 += 320) {
                    pre1[2*i2]   = g_tp1[b*XBC + i2];
                    pre1[2*i2+1] = xt[b*XBC + i2];
                }
                for (int i2 = tid; i2 < 4000; i2 += 320) {
                    int w = i2 / 400, k = i2 % 400;
                    int src = b*12000 + (jg*10 + w)*A1 + k;
                    posts2[2*i2]   = g_z2[src];
                    posts2[2*i2+1] = g_to1[src];
                }
                __syncthreads();
                const float* pr = &posts2[2 * (wid*400)];
                for (int oh = 0; oh < 20; oh++) {
                    int kb = oh*20, ob = oh*24;
                    #pragma unroll 4
                    for (int ow = 0; ow < 20; ow++) {
                        float2 po = *(const float2*)&pr[2*(kb + ow)];
                        float zp = po.x * ETA_P;
                        float tm = po.y * ETA_M;
                        int kofs = ob + ow;
                        float2 pc0 = *(const float2*)&pre1[2*(ib0 + kofs)];
                        a0 = fmaf(zp, pc0.x, a0);
                        a0 = fmaf(-tm, pc0.y, a0);
                        if (v1ok) {
                            float2 pc1 = *(const float2*)&pre1[2*(ib1 + kofs)];
                            a1 = fmaf(zp, pc1.x, a1);
                            a1 = fmaf(-tm, pc1.y, a1);
                        }
                    }
                }
            }
            g_dw1p[bch*1500 + j*50 + i0] = a0;
            if (v1ok) g_dw1p[bch*1500 + j*50 + i1] = a1;
        }
    } else {
        // ---- dw2: 10 jtiles x 64 bchunks(4 b); warp = j, lane covers i strided ----
        int r = bi - DW1CH;
        int jt = r % 10, bch = r / 10;
        float* pp   = smem;          // 2*3000 interleaved (tp2, z3)
        float* z5s  = smem + 6000;   // 360
        float* to2s = smem + 6360;   // 360
        int j = jt*10 + wid;

        int ibase[24];
        #pragma unroll
        for (int m = 0; m < 24; m++) {
            int i = ti + 32*m;
            if (i < 750) {
                int ic = i / 25, rr = i % 25;
                ibase[m] = ic*100 + (rr/5)*10 + (rr%5);
            } else ibase[m] = 0;
        }
        float acc[24];
        #pragma unroll
        for (int m = 0; m < 24; m++) acc[m] = 0.f;

        for (int bb = 0; bb < 4; bb++) {
            int b = bch*4 + bb;
            __syncthreads();
            for (int i2 = tid; i2 < 3000; i2 += 320) {
                float2 v; v.x = g_tp2[b*3000 + i2]; v.y = g_z3[b*3000 + i2];
                *(float2*)&pp[2*i2] = v;
            }
            for (int i2 = tid; i2 < 360; i2 += 320) {
                int src = b*3600 + jt*360 + i2;
                z5s[i2]  = g_z5[src];
                to2s[i2] = g_to2[src];
            }
            __syncthreads();
            const float* zr = &z5s[wid*36];
            const float* tr = &to2s[wid*36];
            for (int oh = 0; oh < 6; oh++) {
                #pragma unroll
                for (int ow = 0; ow < 6; ow++) {
                    int k = oh*6 + ow, kofs = oh*10 + ow;
                    float zp = zr[k] * ETA_P;
                    float tm = tr[k] * ETA_M;
                    #pragma unroll
                    for (int m = 0; m < 24; m++) {
                        float2 pc = *(const float2*)&pp[2*(ibase[m] + kofs)];
                        acc[m] = fmaf(zp, pc.x, acc[m]);
                        acc[m] = fmaf(-tm, pc.y, acc[m]);
                    }
                }
            }
        }
        float* dst = &g_dw2p[(size_t)bch*75000 + j*750];
        #pragma unroll
        for (int m = 0; m < 24; m++) {
            int i = ti + 32*m;
            if (i < 750) dst[i] = acc[m];
        }
    }
}

// ---------------- K6: reduce dw + weight update + FC/LI readout ----------------
__global__ void k6_finish(const float* __restrict__ fc1w, const float* __restrict__ fc1b,
                          const float* __restrict__ outw, float* __restrict__ out, int t) {
    int bi = blockIdx.x, tid = threadIdx.x;
    if (bi < 293) {
        int c = bi*256 + tid;
        if (c < 75000) {
            float s = 0.f;
            #pragma unroll 8
            for (int ch = 0; ch < DW2CH; ch++) s += g_dw2p[(size_t)ch*75000 + c];
            float w = g_w2[c] + s;
            g_w2[c] = fminf(fmaxf(w, 0.f), 1.f);
        }
    } else if (bi < 299) {
        int c = (bi - 293)*256 + tid;
        if (c < 1500) {
            float s = 0.f;
            #pragma unroll 8
            for (int ch = 0; ch < DW1CH; ch++) s += g_dw1p[ch*1500 + c];
            float w = g_w1[c] + s;
            g_w1[c] = fminf(fmaxf(w, 0.f), 1.f);
        }
    } else {
        int b = bi - 299;
        __shared__ float z6s[100], hs[50];
        if (tid < 100) z6s[tid] = g_z6[b*100 + tid];
        __syncthreads();
        if (tid < 50) {
            float a = fc1b[tid];
            const float* wr = &fc1w[tid*100];
            #pragma unroll 4
            for (int k = 0; k < 100; k++) a = fmaf(z6s[k], wr[k], a);
            hs[tid] = fmaxf(a, 0.f);
        }
        __syncthreads();
        if (tid < 10) {
            int idx = b*10 + tid;
            float iold = g_lii[idx], vold = g_liv[idx];
            float vnew = vold + 0.1f * (iold - vold);
            float a = 0.f;
            const float* wr = &outw[tid*50];
            #pragma unroll
            for (int j = 0; j < 50; j++) a = fmaf(hs[j], wr[j], a);
            g_liv[idx] = vnew;
            g_lii[idx] = 0.8f * iold + a;
            out[t*2560 + idx] = vnew;
        }
    }
}

// ---------------- launcher ----------------
extern "C" void kernel_launch(void* const* d_in, const int* in_sizes, int n_in,
                              void* d_out, int out_size) {
    const float* x     = (const float*)d_in[0];
    const float* w1    = (const float*)d_in[1];
    const float* w2    = (const float*)d_in[2];
    const float* fc1_w = (const float*)d_in[3];
    const float* fc1_b = (const float*)d_in[4];
    const float* out_w = (const float*)d_in[5];
    float* out = (float*)d_out;

    k_init<<<(L1SZ + 255) / 256, 256>>>(w1, w2);
    for (int t = 0; t < T; t++) {
        k1_conv1<<<B + 36, 256>>>(x, t);
        k2_pool<<<3000, 256>>>();
        k3_conv2<<<B, 128>>>();
        k45_stdp<<<DW1CH + 640, 320>>>(x, t);
        k6_finish<<<555, 256>>>(fc1_w, fc1_b, out_w, out, t);
    }
}

// round 3
// speedup vs baseline: 1.6934x; 1.6934x over previous
#include <cuda_runtime.h>
#include <cuda_bf16.h>
#include <cstdint>

// ---------------- constants ----------------
#define B       256
#define T       32
#define XBC     1152        // 2*24*24
#define XT      (B*XBC)
#define A1      400         // 20*20
#define L1SZ    (B*30*A1)   // 3,072,000
#define L3SZ    (B*30*100)  // 768,000
#define L2SZ    (B*100*36)  // 921,600
#define DW1CH   128         // 2 batches per chunk
#define DW2CH   64          // 4 batches per chunk

#define VTH1    15.0f
#define VTH2    10.0f
#define DEC     0.02f
#define ETA_P   0.004f
#define ETA_M   0.003f

// ---------------- persistent device state ----------------
__device__ float g_w1[1500];
__device__ float g_w2[75000];
__device__ float g_v1[L1SZ];
__device__ float g_v2[L2SZ];
__device__ float g_tp1[XT];
__device__ float g_to1[L1SZ];
__device__ float g_tp2[L3SZ];
__device__ float g_to2[L2SZ];
__device__ float g_z2[L1SZ];
__device__ float g_z3[L3SZ];
__device__ float g_z5[L2SZ];
__device__ float g_z6[B*100];
__device__ float g_liv[B*10];
__device__ float g_lii[B*10];
__device__ float g_dw1p[DW1CH*1500];
__device__ float g_dw2p[DW2CH*75000];

// ---------------- init ----------------
__global__ void k_init(const float* __restrict__ w1, const float* __restrict__ w2) {
    int i = blockIdx.x * blockDim.x + threadIdx.x;
    if (i < L1SZ) { g_v1[i] = 0.f; g_to1[i] = 0.f; }
    if (i < L2SZ) { g_v2[i] = 0.f; g_to2[i] = 0.f; }
    if (i < XT)   g_tp1[i] = 0.f;
    if (i < L3SZ) g_tp2[i] = 0.f;
    if (i < B*10) { g_liv[i] = 0.f; g_lii[i] = 0.f; }
    if (i < 1500)  g_w1[i] = w1[i];
    if (i < 75000) g_w2[i] = w2[i];
}

// ---------------- K1: conv1 + IAF + to1 trace + fused pool/tp2; extra blocks: tp1 ----------------
__global__ void k1_conv1(const float* __restrict__ x, int t) {
    const float* xt = x + (size_t)t * XT;
    int tid = threadIdx.x;
    if (blockIdx.x >= B) {
        int base = (blockIdx.x - B) * 8192;
        #pragma unroll 4
        for (int r = 0; r < 32; r++) {
            int i = base + r * 256 + tid;
            float tt = g_tp1[i];
            g_tp1[i] = tt - DEC * tt + xt[i];
        }
        return;
    }
    int b = blockIdx.x;
    __shared__ float xs[XBC];
    __shared__ float w1T[50 * 32];
    for (int i = tid; i < XBC; i += 256) xs[i] = xt[b * XBC + i];
    for (int i = tid; i < 1600; i += 256) {
        int c = i >> 5, oc = i & 31;
        w1T[i] = (oc < 30) ? g_w1[oc * 50 + c] : 0.f;
    }
    __syncthreads();

    for (int p = tid; p < A1; p += 256) {
        int oh = p / 20, ow = p % 20;
        float patch[50];
        #pragma unroll
        for (int ic = 0; ic < 2; ic++)
            #pragma unroll
            for (int kh = 0; kh < 5; kh++)
                #pragma unroll
                for (int kw = 0; kw < 5; kw++)
                    patch[ic*25 + kh*5 + kw] = xs[ic*576 + (oh+kh)*24 + ow + kw];

        for (int g = 0; g < 8; g++) {
            float a0=0.f, a1=0.f, a2=0.f, a3=0.f;
            #pragma unroll
            for (int c = 0; c < 50; c++) {
                float4 w = *(const float4*)&w1T[c*32 + g*4];
                a0 = fmaf(patch[c], w.x, a0);
                a1 = fmaf(patch[c], w.y, a1);
                a2 = fmaf(patch[c], w.z, a2);
                a3 = fmaf(patch[c], w.w, a3);
            }
            float av[4] = {a0, a1, a2, a3};
            #pragma unroll
            for (int q = 0; q < 4; q++) {
                int oc = g*4 + q;
                if (oc < 30) {
                    int idx = b*12000 + oc*A1 + p;
                    float v = g_v1[idx] + av[q];
                    float z = (v > VTH1) ? 1.f : 0.f;
                    g_v1[idx] = v * (1.f - z);
                    g_z2[idx] = z;
                    float tt = g_to1[idx];
                    g_to1[idx] = tt - DEC * tt + z;
                }
            }
        }
    }
    // fused maxpool 2x2 + tp2 trace (z2 visible after barrier)
    __syncthreads();
    for (int e = tid; e < 3000; e += 256) {
        int c = e / 100, q = e % 100;
        int oh = q / 10, ow = q % 10;
        int base = b*12000 + c*A1 + oh*40 + ow*2;
        float m = fmaxf(fmaxf(g_z2[base], g_z2[base+1]),
                        fmaxf(g_z2[base+20], g_z2[base+21]));
        int o = b*3000 + e;
        g_z3[o] = m;
        float tt = g_tp2[o];
        g_tp2[o] = tt - DEC * tt + m;
    }
}

// ---------------- K3: conv2 (x10) + IAF + to2 trace + z6 (600 threads = 100 oc x 6 oh) ----------------
__global__ void k3_conv2(void) {
    __shared__ float z3s[3000];
    __shared__ float w2s[7500];
    int b = blockIdx.x, tid = threadIdx.x;
    for (int i = tid; i < 3000; i += 600) z3s[i] = g_z3[b*3000 + i];

    int oc = tid % 100, ohh = tid / 100;   // ohh in 0..5
    float acc[6] = {0.f,0.f,0.f,0.f,0.f,0.f};

    for (int ic0 = 0; ic0 < 30; ic0 += 3) {
        __syncthreads();
        for (int i = tid; i < 7500; i += 600) {
            int o2 = i / 75, cc = i % 75;
            w2s[i] = g_w2[o2*750 + ic0*25 + cc];
        }
        __syncthreads();
        #pragma unroll
        for (int icl = 0; icl < 3; icl++) {
            const float* zb = &z3s[(ic0 + icl)*100];
            const float* wb = &w2s[oc*75 + icl*25];
            #pragma unroll
            for (int kh = 0; kh < 5; kh++) {
                float r[10];
                const float* zrow = &zb[(ohh + kh)*10];
                #pragma unroll
                for (int u = 0; u < 5; u++) {
                    float2 v = *(const float2*)&zrow[2*u];
                    r[2*u] = v.x; r[2*u+1] = v.y;
                }
                #pragma unroll
                for (int kw = 0; kw < 5; kw++) {
                    float w = wb[kh*5 + kw];
                    #pragma unroll
                    for (int ow = 0; ow < 6; ow++)
                        acc[ow] = fmaf(w, r[ow + kw], acc[ow]);
                }
            }
        }
    }
    // IAF epilogue: thread owns 6 consecutive outputs
    float zmax = 0.f;
    int obase = b*3600 + oc*36 + ohh*6;
    #pragma unroll
    for (int ow = 0; ow < 6; ow++) {
        int idx = obase + ow;
        float v = g_v2[idx] + 10.0f * acc[ow];
        float z = (v > VTH2) ? 1.f : 0.f;
        g_v2[idx] = v * (1.f - z);
        g_z5[idx] = z;
        float tt = g_to2[idx];
        g_to2[idx] = tt - DEC * tt + z;
        zmax = fmaxf(zmax, z);
    }
    __syncthreads();
    w2s[ohh*100 + oc] = zmax;
    __syncthreads();
    if (tid < 100) {
        float m = 0.f;
        #pragma unroll
        for (int k2 = 0; k2 < 6; k2++) m = fmaxf(m, w2s[k2*100 + tid]);
        g_z6[b*100 + tid] = m;
    }
}

// ---------------- K45: STDP weight-gradient partials (dw1 3j/warp, dw2 2j/warp) ----------------
__global__ void __launch_bounds__(320, 2) k45_stdp(const float* __restrict__ x, int t) {
    __shared__ float smem[7440];
    int bi = blockIdx.x, tid = threadIdx.x;
    int wid = tid >> 5, ti = tid & 31;
    const float* xt = x + (size_t)t * XT;

    if (bi < DW1CH) {
        // ---- dw1: block = 2 batches; warp wid handles j = wid, wid+10, wid+20 ----
        float* pre1 = smem;   // 2*1152 interleaved (tp1, x)
        int bch = bi;
        int i0 = ti;
        int ib0 = (i0/25)*576 + ((i0%25)/5)*24 + (i0%5);
        bool v1ok = (ti < 18);
        int i1 = ti + 32;
        int ib1 = v1ok ? (i1/25)*576 + ((i1%25)/5)*24 + (i1%5) : 0;

        float a00=0.f,a01=0.f,a10=0.f,a11=0.f,a20=0.f,a21=0.f;
        for (int bb = 0; bb < 2; bb++) {
            int b = bch*2 + bb;
            __syncthreads();
            for (int i2 = tid; i2 < XBC; i2 += 320) {
                pre1[2*i2]   = g_tp1[b*XBC + i2];
                pre1[2*i2+1] = xt[b*XBC + i2];
            }
            __syncthreads();
            const float* za = &g_z2[b*12000 + wid*400];
            const float* zbp = &g_z2[b*12000 + (wid+10)*400];
            const float* zc = &g_z2[b*12000 + (wid+20)*400];
            const float* ta = &g_to1[b*12000 + wid*400];
            const float* tb = &g_to1[b*12000 + (wid+10)*400];
            const float* tc = &g_to1[b*12000 + (wid+20)*400];

            for (int oh = 0; oh < 20; oh++) {
                int kb = oh*20, ob = oh*24;
                #pragma unroll
                for (int og = 0; og < 5; og++) {
                    float4 z4a = *(const float4*)&za[kb + og*4];
                    float4 z4b = *(const float4*)&zbp[kb + og*4];
                    float4 z4c = *(const float4*)&zc[kb + og*4];
                    float4 t4a = *(const float4*)&ta[kb + og*4];
                    float4 t4b = *(const float4*)&tb[kb + og*4];
                    float4 t4c = *(const float4*)&tc[kb + og*4];
                    const float* zfa = &z4a.x; const float* zfb = &z4b.x; const float* zfc = &z4c.x;
                    const float* tfa = &t4a.x; const float* tfb = &t4b.x; const float* tfc = &t4c.x;
                    #pragma unroll
                    for (int oi = 0; oi < 4; oi++) {
                        int kofs = ob + og*4 + oi;
                        float2 pc0 = *(const float2*)&pre1[2*(ib0 + kofs)];
                        float px0 = pc0.x * ETA_P, py0 = pc0.y * ETA_M;
                        a00 = fmaf(zfa[oi], px0, a00); a00 = fmaf(-tfa[oi], py0, a00);
                        a10 = fmaf(zfb[oi], px0, a10); a10 = fmaf(-tfb[oi], py0, a10);
                        a20 = fmaf(zfc[oi], px0, a20); a20 = fmaf(-tfc[oi], py0, a20);
                        if (v1ok) {
                            float2 pc1 = *(const float2*)&pre1[2*(ib1 + kofs)];
                            float px1 = pc1.x * ETA_P, py1 = pc1.y * ETA_M;
                            a01 = fmaf(zfa[oi], px1, a01); a01 = fmaf(-tfa[oi], py1, a01);
                            a11 = fmaf(zfb[oi], px1, a11); a11 = fmaf(-tfb[oi], py1, a11);
                            a21 = fmaf(zfc[oi], px1, a21); a21 = fmaf(-tfc[oi], py1, a21);
                        }
                    }
                }
            }
        }
        int base = bch*1500;
        g_dw1p[base + wid*50 + i0]      = a00;
        g_dw1p[base + (wid+10)*50 + i0] = a10;
        g_dw1p[base + (wid+20)*50 + i0] = a20;
        if (v1ok) {
            g_dw1p[base + wid*50 + i1]      = a01;
            g_dw1p[base + (wid+10)*50 + i1] = a11;
            g_dw1p[base + (wid+20)*50 + i1] = a21;
        }
    } else {
        // ---- dw2: 5 jtiles(20 j) x 64 bchunks(4 b); warp handles j1=jt*20+wid, j2=j1+10 ----
        int r = bi - DW1CH;
        int jt = r % 5, bch = r / 5;
        float* pp   = smem;          // 2*3000 interleaved (tp2, z3)
        float* z5s  = smem + 6000;   // 720
        float* to2s = smem + 6720;   // 720

        int ibase[24];
        #pragma unroll
        for (int m = 0; m < 24; m++) {
            int i = ti + 32*m;
            ibase[m] = (i < 750) ? (i/25)*100 + ((i%25)/5)*10 + (i%5) : 0;
        }
        float acc1[24], acc2[24];
        #pragma unroll
        for (int m = 0; m < 24; m++) { acc1[m] = 0.f; acc2[m] = 0.f; }

        for (int bb = 0; bb < 4; bb++) {
            int b = bch*4 + bb;
            __syncthreads();
            for (int i2 = tid; i2 < 3000; i2 += 320) {
                float2 v; v.x = g_tp2[b*3000 + i2]; v.y = g_z3[b*3000 + i2];
                *(float2*)&pp[2*i2] = v;
            }
            for (int i2 = tid; i2 < 720; i2 += 320) {
                int src = b*3600 + jt*720 + i2;
                z5s[i2]  = g_z5[src];
                to2s[i2] = g_to2[src];
            }
            __syncthreads();
            const float* zr1 = &z5s[wid*36];
            const float* zr2 = &z5s[(wid+10)*36];
            const float* tr1 = &to2s[wid*36];
            const float* tr2 = &to2s[(wid+10)*36];
            for (int oh = 0; oh < 6; oh++) {
                #pragma unroll
                for (int ow = 0; ow < 6; ow++) {
                    int k = oh*6 + ow, kofs = oh*10 + ow;
                    float zp1 = zr1[k]*ETA_P, tm1 = tr1[k]*ETA_M;
                    float zp2 = zr2[k]*ETA_P, tm2 = tr2[k]*ETA_M;
                    #pragma unroll
                    for (int m = 0; m < 24; m++) {
                        float2 pc = *(const float2*)&pp[2*(ibase[m] + kofs)];
                        acc1[m] = fmaf(zp1, pc.x, acc1[m]);
                        acc1[m] = fmaf(-tm1, pc.y, acc1[m]);
                        acc2[m] = fmaf(zp2, pc.x, acc2[m]);
                        acc2[m] = fmaf(-tm2, pc.y, acc2[m]);
                    }
                }
            }
        }
        int j1 = jt*20 + wid, j2 = j1 + 10;
        float* d1 = &g_dw2p[(size_t)bch*75000 + j1*750];
        float* d2 = &g_dw2p[(size_t)bch*75000 + j2*750];
        #pragma unroll
        for (int m = 0; m < 24; m++) {
            int i = ti + 32*m;
            if (i < 750) { d1[i] = acc1[m]; d2[i] = acc2[m]; }
        }
    }
}

// ---------------- K6: reduce dw + weight update + FC/LI readout ----------------
__global__ void k6_finish(const float* __restrict__ fc1w, const float* __restrict__ fc1b,
                          const float* __restrict__ outw, float* __restrict__ out, int t) {
    int bi = blockIdx.x, tid = threadIdx.x;
    if (bi < 293) {
        int c = bi*256 + tid;
        if (c < 75000) {
            float s = 0.f;
            #pragma unroll 8
            for (int ch = 0; ch < DW2CH; ch++) s += g_dw2p[(size_t)ch*75000 + c];
            float w = g_w2[c] + s;
            g_w2[c] = fminf(fmaxf(w, 0.f), 1.f);
        }
    } else if (bi < 299) {
        int c = (bi - 293)*256 + tid;
        if (c < 1500) {
            float s = 0.f;
            #pragma unroll 8
            for (int ch = 0; ch < DW1CH; ch++) s += g_dw1p[ch*1500 + c];
            float w = g_w1[c] + s;
            g_w1[c] = fminf(fmaxf(w, 0.f), 1.f);
        }
    } else {
        int b = bi - 299;
        __shared__ float z6s[100], hs[50];
        if (tid < 100) z6s[tid] = g_z6[b*100 + tid];
        __syncthreads();
        if (tid < 50) {
            float a = fc1b[tid];
            const float* wr = &fc1w[tid*100];
            #pragma unroll 4
            for (int k = 0; k < 100; k++) a = fmaf(z6s[k], wr[k], a);
            hs[tid] = fmaxf(a, 0.f);
        }
        __syncthreads();
        if (tid < 10) {
            int idx = b*10 + tid;
            float iold = g_lii[idx], vold = g_liv[idx];
            float vnew = vold + 0.1f * (iold - vold);
            float a = 0.f;
            const float* wr = &outw[tid*50];
            #pragma unroll
            for (int j = 0; j < 50; j++) a = fmaf(hs[j], wr[j], a);
            g_liv[idx] = vnew;
            g_lii[idx] = 0.8f * iold + a;
            out[t*2560 + idx] = vnew;
        }
    }
}

// ---------------- launcher ----------------
extern "C" void kernel_launch(void* const* d_in, const int* in_sizes, int n_in,
                              void* d_out, int out_size) {
    const float* x     = (const float*)d_in[0];
    const float* w1    = (const float*)d_in[1];
    const float* w2    = (const float*)d_in[2];
    const float* fc1_w = (const float*)d_in[3];
    const float* fc1_b = (const float*)d_in[4];
    const float* out_w = (const float*)d_in[5];
    float* out = (float*)d_out;

    k_init<<<(L1SZ + 255) / 256, 256>>>(w1, w2);
    for (int t = 0; t < T; t++) {
        k1_conv1<<<B + 36, 256>>>(x, t);
        k3_conv2<<<B, 600>>>();
        k45_stdp<<<DW1CH + 320, 320>>>(x, t);
        k6_finish<<<555, 256>>>(fc1_w, fc1_b, out_w, out, t);
    }
}

// round 4
// speedup vs baseline: 2.3000x; 1.3582x over previous
#include <cuda_runtime.h>
#include <cuda_bf16.h>
#include <cstdint>

// ---------------- constants ----------------
#define B       256
#define T       32
#define XBC     1152        // 2*24*24
#define XT      (B*XBC)
#define A1      400         // 20*20
#define L1SZ    (B*30*A1)   // 3,072,000
#define L3SZ    (B*30*100)  // 768,000
#define L2SZ    (B*100*36)  // 921,600
#define DW1CH   128         // 2 batches per chunk
#define DW2CH   32          // 8 batches per chunk

#define VTH1    15.0f
#define VTH2    10.0f
#define DEC     0.02f
#define ETA_P   0.004f
#define ETA_M   0.003f

// ---------------- persistent device state ----------------
__device__ float g_w1[1500];
__device__ float g_w2[75000];
__device__ float g_v1[L1SZ];
__device__ float g_v2[L2SZ];
__device__ float g_tp1[XT];
__device__ float g_to1[L1SZ];
__device__ float g_tp2[L3SZ];
__device__ float g_to2[L2SZ];
__device__ float g_z2[L1SZ];
__device__ float g_z3[L3SZ];
__device__ float g_z5[L2SZ];
__device__ float g_z6[B*100];
__device__ float g_liv[B*10];
__device__ float g_lii[B*10];
__device__ float g_dw1p[DW1CH*1500];
__device__ float g_dw2p[DW2CH*75000];

// ---------------- init ----------------
__global__ void k_init(const float* __restrict__ w1, const float* __restrict__ w2) {
    int i = blockIdx.x * blockDim.x + threadIdx.x;
    if (i < L1SZ) { g_v1[i] = 0.f; g_to1[i] = 0.f; }
    if (i < L2SZ) { g_v2[i] = 0.f; g_to2[i] = 0.f; }
    if (i < XT)   g_tp1[i] = 0.f;
    if (i < L3SZ) g_tp2[i] = 0.f;
    if (i < B*10) { g_liv[i] = 0.f; g_lii[i] = 0.f; }
    if (i < 1500)  g_w1[i] = w1[i];
    if (i < 75000) g_w2[i] = w2[i];
}

// ---------------- K1: conv1 + IAF + to1 trace + fused pool/tp2; extra blocks: tp1 ----------------
__global__ void k1_conv1(const float* __restrict__ x, int t) {
    const float* xt = x + (size_t)t * XT;
    int tid = threadIdx.x;
    if (blockIdx.x >= B) {
        int base = (blockIdx.x - B) * 8192;
        #pragma unroll 4
        for (int r = 0; r < 32; r++) {
            int i = base + r * 256 + tid;
            float tt = g_tp1[i];
            g_tp1[i] = tt - DEC * tt + xt[i];
        }
        return;
    }
    int b = blockIdx.x;
    __shared__ float xs[XBC];
    __shared__ float w1T[50 * 32];
    for (int i = tid; i < XBC; i += 256) xs[i] = xt[b * XBC + i];
    for (int i = tid; i < 1600; i += 256) {
        int c = i >> 5, oc = i & 31;
        w1T[i] = (oc < 30) ? g_w1[oc * 50 + c] : 0.f;
    }
    __syncthreads();

    for (int p = tid; p < A1; p += 256) {
        int oh = p / 20, ow = p % 20;
        float patch[50];
        #pragma unroll
        for (int ic = 0; ic < 2; ic++)
            #pragma unroll
            for (int kh = 0; kh < 5; kh++)
                #pragma unroll
                for (int kw = 0; kw < 5; kw++)
                    patch[ic*25 + kh*5 + kw] = xs[ic*576 + (oh+kh)*24 + ow + kw];

        for (int g = 0; g < 8; g++) {
            float a0=0.f, a1=0.f, a2=0.f, a3=0.f;
            #pragma unroll
            for (int c = 0; c < 50; c++) {
                float4 w = *(const float4*)&w1T[c*32 + g*4];
                a0 = fmaf(patch[c], w.x, a0);
                a1 = fmaf(patch[c], w.y, a1);
                a2 = fmaf(patch[c], w.z, a2);
                a3 = fmaf(patch[c], w.w, a3);
            }
            float av[4] = {a0, a1, a2, a3};
            #pragma unroll
            for (int q = 0; q < 4; q++) {
                int oc = g*4 + q;
                if (oc < 30) {
                    int idx = b*12000 + oc*A1 + p;
                    float v = g_v1[idx] + av[q];
                    float z = (v > VTH1) ? 1.f : 0.f;
                    g_v1[idx] = v * (1.f - z);
                    g_z2[idx] = z;
                    float tt = g_to1[idx];
                    g_to1[idx] = tt - DEC * tt + z;
                }
            }
        }
    }
    // fused maxpool 2x2 + tp2 trace (z2 visible after barrier)
    __syncthreads();
    for (int e = tid; e < 3000; e += 256) {
        int c = e / 100, q = e % 100;
        int oh = q / 10, ow = q % 10;
        int base = b*12000 + c*A1 + oh*40 + ow*2;
        float m = fmaxf(fmaxf(g_z2[base], g_z2[base+1]),
                        fmaxf(g_z2[base+20], g_z2[base+21]));
        int o = b*3000 + e;
        g_z3[o] = m;
        float tt = g_tp2[o];
        g_tp2[o] = tt - DEC * tt + m;
    }
}

// ---------------- K3: conv2 (x10) + IAF + to2 trace + z6 (600 threads = 100 oc x 6 oh) ----------------
__global__ void k3_conv2(void) {
    __shared__ float z3s[3000];
    __shared__ float w2s[7500];
    int b = blockIdx.x, tid = threadIdx.x;
    for (int i = tid; i < 3000; i += 600) z3s[i] = g_z3[b*3000 + i];

    int oc = tid % 100, ohh = tid / 100;   // ohh in 0..5
    float acc[6] = {0.f,0.f,0.f,0.f,0.f,0.f};

    for (int ic0 = 0; ic0 < 30; ic0 += 3) {
        __syncthreads();
        for (int i = tid; i < 7500; i += 600) {
            int o2 = i / 75, cc = i % 75;
            w2s[i] = g_w2[o2*750 + ic0*25 + cc];
        }
        __syncthreads();
        #pragma unroll
        for (int icl = 0; icl < 3; icl++) {
            const float* zb = &z3s[(ic0 + icl)*100];
            const float* wb = &w2s[oc*75 + icl*25];
            #pragma unroll
            for (int kh = 0; kh < 5; kh++) {
                float r[10];
                const float* zrow = &zb[(ohh + kh)*10];
                #pragma unroll
                for (int u = 0; u < 5; u++) {
                    float2 v = *(const float2*)&zrow[2*u];
                    r[2*u] = v.x; r[2*u+1] = v.y;
                }
                #pragma unroll
                for (int kw = 0; kw < 5; kw++) {
                    float w = wb[kh*5 + kw];
                    #pragma unroll
                    for (int ow = 0; ow < 6; ow++)
                        acc[ow] = fmaf(w, r[ow + kw], acc[ow]);
                }
            }
        }
    }
    float zmax = 0.f;
    int obase = b*3600 + oc*36 + ohh*6;
    #pragma unroll
    for (int ow = 0; ow < 6; ow++) {
        int idx = obase + ow;
        float v = g_v2[idx] + 10.0f * acc[ow];
        float z = (v > VTH2) ? 1.f : 0.f;
        g_v2[idx] = v * (1.f - z);
        g_z5[idx] = z;
        float tt = g_to2[idx];
        g_to2[idx] = tt - DEC * tt + z;
        zmax = fmaxf(zmax, z);
    }
    __syncthreads();
    w2s[ohh*100 + oc] = zmax;
    __syncthreads();
    if (tid < 100) {
        float m = 0.f;
        #pragma unroll
        for (int k2 = 0; k2 < 6; k2++) m = fmaxf(m, w2s[k2*100 + tid]);
        g_z6[b*100 + tid] = m;
    }
}

// ---------------- K45: STDP weight-gradient partials (dw1 3j/warp, dw2 4j x 12i /warp) ----------------
__global__ void __launch_bounds__(320, 2) k45_stdp(const float* __restrict__ x, int t) {
    __shared__ float smem[7440];
    int bi = blockIdx.x, tid = threadIdx.x;
    int wid = tid >> 5, ti = tid & 31;
    const float* xt = x + (size_t)t * XT;

    if (bi < DW1CH) {
        // ---- dw1: block = 2 batches; warp wid handles j = wid, wid+10, wid+20 ----
        float* pre1 = smem;   // 2*1152 interleaved (tp1, x)
        int bch = bi;
        int i0 = ti;
        int ib0 = (i0/25)*576 + ((i0%25)/5)*24 + (i0%5);
        bool v1ok = (ti < 18);
        int i1 = ti + 32;
        int ib1 = v1ok ? (i1/25)*576 + ((i1%25)/5)*24 + (i1%5) : 0;

        float a00=0.f,a01=0.f,a10=0.f,a11=0.f,a20=0.f,a21=0.f;
        for (int bb = 0; bb < 2; bb++) {
            int b = bch*2 + bb;
            __syncthreads();
            for (int i2 = tid; i2 < XBC; i2 += 320) {
                pre1[2*i2]   = g_tp1[b*XBC + i2];
                pre1[2*i2+1] = xt[b*XBC + i2];
            }
            __syncthreads();
            const float* za = &g_z2[b*12000 + wid*400];
            const float* zbp = &g_z2[b*12000 + (wid+10)*400];
            const float* zc = &g_z2[b*12000 + (wid+20)*400];
            const float* ta = &g_to1[b*12000 + wid*400];
            const float* tb = &g_to1[b*12000 + (wid+10)*400];
            const float* tc = &g_to1[b*12000 + (wid+20)*400];

            for (int oh = 0; oh < 20; oh++) {
                int kb = oh*20, ob = oh*24;
                #pragma unroll
                for (int og = 0; og < 5; og++) {
                    float4 z4a = *(const float4*)&za[kb + og*4];
                    float4 z4b = *(const float4*)&zbp[kb + og*4];
                    float4 z4c = *(const float4*)&zc[kb + og*4];
                    float4 t4a = *(const float4*)&ta[kb + og*4];
                    float4 t4b = *(const float4*)&tb[kb + og*4];
                    float4 t4c = *(const float4*)&tc[kb + og*4];
                    const float* zfa = &z4a.x; const float* zfb = &z4b.x; const float* zfc = &z4c.x;
                    const float* tfa = &t4a.x; const float* tfb = &t4b.x; const float* tfc = &t4c.x;
                    #pragma unroll
                    for (int oi = 0; oi < 4; oi++) {
                        int kofs = ob + og*4 + oi;
                        float2 pc0 = *(const float2*)&pre1[2*(ib0 + kofs)];
                        float px0 = pc0.x * ETA_P, py0 = pc0.y * ETA_M;
                        a00 = fmaf(zfa[oi], px0, a00); a00 = fmaf(-tfa[oi], py0, a00);
                        a10 = fmaf(zfb[oi], px0, a10); a10 = fmaf(-tfb[oi], py0, a10);
                        a20 = fmaf(zfc[oi], px0, a20); a20 = fmaf(-tfc[oi], py0, a20);
                        if (v1ok) {
                            float2 pc1 = *(const float2*)&pre1[2*(ib1 + kofs)];
                            float px1 = pc1.x * ETA_P, py1 = pc1.y * ETA_M;
                            a01 = fmaf(zfa[oi], px1, a01); a01 = fmaf(-tfa[oi], py1, a01);
                            a11 = fmaf(zfb[oi], px1, a11); a11 = fmaf(-tfb[oi], py1, a11);
                            a21 = fmaf(zfc[oi], px1, a21); a21 = fmaf(-tfc[oi], py1, a21);
                        }
                    }
                }
            }
        }
        int base = bch*1500;
        g_dw1p[base + wid*50 + i0]      = a00;
        g_dw1p[base + (wid+10)*50 + i0] = a10;
        g_dw1p[base + (wid+20)*50 + i0] = a20;
        if (v1ok) {
            g_dw1p[base + wid*50 + i1]      = a01;
            g_dw1p[base + (wid+10)*50 + i1] = a11;
            g_dw1p[base + (wid+20)*50 + i1] = a21;
        }
    } else {
        // ---- dw2: 5 jtiles(20 j) x 32 bchunks(8 b) ----
        // warp = (iw = wid/5 in {0,1}, jw = wid%5); handles 4 j = jt*20+jw*4+q, 12 i = ti+32*(iw*12+m)
        int r = bi - DW1CH;
        int jt = r % 5, bch = r / 5;
        float* pp   = smem;          // 2*3000 interleaved (tp2, z3)
        float* z5s  = smem + 6000;   // 720 (20 j x 36 k)
        float* to2s = smem + 6720;   // 720
        int iw = wid / 5, jw = wid % 5;
        int jl0 = jw * 4;            // local j base within jtile

        int ibase[12];
        bool vm[12];
        #pragma unroll
        for (int m = 0; m < 12; m++) {
            int i = ti + 32*(iw*12 + m);
            vm[m] = (i < 750);
            ibase[m] = vm[m] ? (i/25)*100 + ((i%25)/5)*10 + (i%5) : 0;
        }
        float acc[4][12];
        #pragma unroll
        for (int q = 0; q < 4; q++)
            #pragma unroll
            for (int m = 0; m < 12; m++) acc[q][m] = 0.f;

        for (int bb = 0; bb < 8; bb++) {
            int b = bch*8 + bb;
            __syncthreads();
            for (int i2 = tid; i2 < 3000; i2 += 320) {
                float2 v; v.x = g_tp2[b*3000 + i2]; v.y = g_z3[b*3000 + i2];
                *(float2*)&pp[2*i2] = v;
            }
            for (int i2 = tid; i2 < 720; i2 += 320) {
                int src = b*3600 + jt*720 + i2;
                z5s[i2]  = g_z5[src];
                to2s[i2] = g_to2[src];
            }
            __syncthreads();
            for (int oh = 0; oh < 6; oh++) {
                #pragma unroll
                for (int ow = 0; ow < 6; ow++) {
                    int k = oh*6 + ow, kofs = oh*10 + ow;
                    float zp[4], tmn[4];
                    #pragma unroll
                    for (int q = 0; q < 4; q++) {
                        zp[q]  = z5s[(jl0+q)*36 + k] * ETA_P;
                        tmn[q] = to2s[(jl0+q)*36 + k] * (-ETA_M);
                    }
                    #pragma unroll
                    for (int m = 0; m < 12; m++) {
                        float2 pc = *(const float2*)&pp[2*(ibase[m] + kofs)];
                        #pragma unroll
                        for (int q = 0; q < 4; q++) {
                            acc[q][m] = fmaf(zp[q],  pc.x, acc[q][m]);
                            acc[q][m] = fmaf(tmn[q], pc.y, acc[q][m]);
                        }
                    }
                }
            }
        }
        size_t pbase = (size_t)bch*75000;
        #pragma unroll
        for (int q = 0; q < 4; q++) {
            int j = jt*20 + jl0 + q;
            float* dst = &g_dw2p[pbase + j*750];
            #pragma unroll
            for (int m = 0; m < 12; m++) {
                int i = ti + 32*(iw*12 + m);
                if (vm[m]) dst[i] = acc[q][m];
            }
        }
    }
}

// ---------------- K6: reduce dw + weight update + FC/LI readout ----------------
__global__ void k6_finish(const float* __restrict__ fc1w, const float* __restrict__ fc1b,
                          const float* __restrict__ outw, float* __restrict__ out, int t) {
    int bi = blockIdx.x, tid = threadIdx.x;
    if (bi < 293) {
        int c = bi*256 + tid;
        if (c < 75000) {
            float s = 0.f;
            #pragma unroll 8
            for (int ch = 0; ch < DW2CH; ch++) s += g_dw2p[(size_t)ch*75000 + c];
            float w = g_w2[c] + s;
            g_w2[c] = fminf(fmaxf(w, 0.f), 1.f);
        }
    } else if (bi < 299) {
        int c = (bi - 293)*256 + tid;
        if (c < 1500) {
            float s = 0.f;
            #pragma unroll 8
            for (int ch = 0; ch < DW1CH; ch++) s += g_dw1p[ch*1500 + c];
            float w = g_w1[c] + s;
            g_w1[c] = fminf(fmaxf(w, 0.f), 1.f);
        }
    } else {
        int b = bi - 299;
        __shared__ float z6s[100], hs[50];
        if (tid < 100) z6s[tid] = g_z6[b*100 + tid];
        __syncthreads();
        if (tid < 50) {
            float a = fc1b[tid];
            const float* wr = &fc1w[tid*100];
            #pragma unroll 4
            for (int k = 0; k < 100; k++) a = fmaf(z6s[k], wr[k], a);
            hs[tid] = fmaxf(a, 0.f);
        }
        __syncthreads();
        if (tid < 10) {
            int idx = b*10 + tid;
            float iold = g_lii[idx], vold = g_liv[idx];
            float vnew = vold + 0.1f * (iold - vold);
            float a = 0.f;
            const float* wr = &outw[tid*50];
            #pragma unroll
            for (int j = 0; j < 50; j++) a = fmaf(hs[j], wr[j], a);
            g_liv[idx] = vnew;
            g_lii[idx] = 0.8f * iold + a;
            out[t*2560 + idx] = vnew;
        }
    }
}

// ---------------- launcher ----------------
extern "C" void kernel_launch(void* const* d_in, const int* in_sizes, int n_in,
                              void* d_out, int out_size) {
    const float* x     = (const float*)d_in[0];
    const float* w1    = (const float*)d_in[1];
    const float* w2    = (const float*)d_in[2];
    const float* fc1_w = (const float*)d_in[3];
    const float* fc1_b = (const float*)d_in[4];
    const float* out_w = (const float*)d_in[5];
    float* out = (float*)d_out;

    k_init<<<(L1SZ + 255) / 256, 256>>>(w1, w2);
    for (int t = 0; t < T; t++) {
        k1_conv1<<<B + 36, 256>>>(x, t);
        k3_conv2<<<B, 600>>>();
        k45_stdp<<<DW1CH + 5*DW2CH, 320>>>(x, t);
        k6_finish<<<555, 256>>>(fc1_w, fc1_b, out_w, out, t);
    }
}